// round 1
// baseline (speedup 1.0000x reference)
#include <cuda_runtime.h>
#include <mma.h>
#include <cstdio>

using namespace nvcuda;

// Problem constants
#define B_    2
#define N_    2048
#define D_    1024
#define H_    16
#define DK_   64
#define M_TOT (B_ * N_)          // 4096 rows for all projection GEMMs
static constexpr float SCALE = 0.125f;   // DK^-0.5

// Scratch (static __device__ arrays — allocation-free per harness rules)
__device__ float g_Q[M_TOT * D_];
__device__ float g_K[M_TOT * D_];
__device__ float g_V[M_TOT * D_];
__device__ float g_AO[M_TOT * D_];

// ---------------------------------------------------------------------------
// GEMM: out[m,n] = sum_k X[m,k] * W[n,k] + bias[n]
// X: [4096,1024] row-major, W: [1024,1024] row-major ("W^T" gemm), tf32 WMMA.
// Block tile 128x128x32, 256 threads (8 warps, 2x4), warp tile 64x32.
// ---------------------------------------------------------------------------
#define BM 128
#define BN 128
#define BK 32
#define LDA_S (BK + 4)   // 36, multiple of 4 for tf32 ldm

__global__ __launch_bounds__(256) void gemm_xwT_bias(
    const float* __restrict__ X, const float* __restrict__ W,
    const float* __restrict__ bias, float* __restrict__ out)
{
    __shared__ float As[BM][LDA_S];
    __shared__ float Bs[BN][LDA_S];
    __shared__ float bias_s[16][BN];

    const int tid = threadIdx.x;
    const int wid = tid >> 5;
    const int m0 = blockIdx.y * BM;
    const int n0 = blockIdx.x * BN;
    const int warp_m = wid >> 2;   // 0..1 -> 64 rows each
    const int warp_n = wid & 3;    // 0..3 -> 32 cols each

    // Bias broadcast tile: 16 identical rows so accumulator frags init = bias
    for (int i = tid; i < 16 * BN; i += 256)
        bias_s[i >> 7][i & 127] = bias[n0 + (i & 127)];
    __syncthreads();

    wmma::fragment<wmma::accumulator, 16, 16, 8, float> c[4][2];
    #pragma unroll
    for (int i = 0; i < 4; i++)
        #pragma unroll
        for (int j = 0; j < 2; j++)
            wmma::load_matrix_sync(c[i][j], &bias_s[0][warp_n * 32 + j * 16],
                                   BN, wmma::mem_row_major);

    const int lrow = tid >> 3;        // 0..31
    const int lc4  = (tid & 7) * 4;   // 0,4,...,28

    for (int k0 = 0; k0 < D_; k0 += BK) {
        __syncthreads();
        #pragma unroll
        for (int r = lrow; r < BM; r += 32)
            *(float4*)&As[r][lc4] =
                *(const float4*)&X[(size_t)(m0 + r) * D_ + k0 + lc4];
        #pragma unroll
        for (int r = lrow; r < BN; r += 32)
            *(float4*)&Bs[r][lc4] =
                *(const float4*)&W[(size_t)(n0 + r) * D_ + k0 + lc4];
        __syncthreads();

        #pragma unroll
        for (int kk = 0; kk < BK; kk += 8) {
            wmma::fragment<wmma::matrix_a, 16, 16, 8, wmma::precision::tf32,
                           wmma::row_major> a[4];
            wmma::fragment<wmma::matrix_b, 16, 16, 8, wmma::precision::tf32,
                           wmma::col_major> b[2];
            #pragma unroll
            for (int i = 0; i < 4; i++) {
                wmma::load_matrix_sync(a[i], &As[warp_m * 64 + i * 16][kk], LDA_S);
                #pragma unroll
                for (int e = 0; e < a[i].num_elements; e++)
                    a[i].x[e] = wmma::__float_to_tf32(a[i].x[e]);
            }
            #pragma unroll
            for (int j = 0; j < 2; j++) {
                wmma::load_matrix_sync(b[j], &Bs[warp_n * 32 + j * 16][kk], LDA_S);
                #pragma unroll
                for (int e = 0; e < b[j].num_elements; e++)
                    b[j].x[e] = wmma::__float_to_tf32(b[j].x[e]);
            }
            #pragma unroll
            for (int i = 0; i < 4; i++)
                #pragma unroll
                for (int j = 0; j < 2; j++)
                    wmma::mma_sync(c[i][j], a[i], b[j], c[i][j]);
        }
    }

    #pragma unroll
    for (int i = 0; i < 4; i++)
        #pragma unroll
        for (int j = 0; j < 2; j++)
            wmma::store_matrix_sync(
                &out[(size_t)(m0 + warp_m * 64 + i * 16) * D_ +
                     n0 + warp_n * 32 + j * 16],
                c[i][j], D_, wmma::mem_row_major);
}

// ---------------------------------------------------------------------------
// Flash attention: one block = 64 queries of one (b,h); loops 64-key tiles.
// QK^T and P*V via tf32 WMMA; online softmax; O accumulated in SMEM fp32.
// ---------------------------------------------------------------------------
#define LDT 72   // 64 + 8 pad, multiple of 4

__global__ __launch_bounds__(256) void attn_kernel()
{
    extern __shared__ float sm[];
    float* Qs  = sm;               // 64*LDT
    float* Ks  = Qs + 64 * LDT;    // 64*LDT  (also reused as PV staging)
    float* Vs  = Ks + 64 * LDT;    // 64*LDT
    float* Ss  = Vs + 64 * LDT;    // 64*LDT  (scores, then probabilities)
    float* Os  = Ss + 64 * LDT;    // 64*64 accumulator
    float* m_s = Os + 64 * 64;     // 64
    float* l_s = m_s + 64;         // 64
    float* sc_s = l_s + 64;        // 64

    const int tid = threadIdx.x;
    const int wid = tid >> 5;
    const int q0  = blockIdx.x * 64;
    const int h   = blockIdx.y;
    const int b   = blockIdx.z;
    const size_t base = (size_t)b * N_ * D_ + (size_t)h * DK_;

    // Load Q tile (pre-scaled by 1/sqrt(DK))
    {
        const int row = tid >> 4;          // 0..15
        const int c4  = (tid & 15) * 4;    // 0..60
        for (int r = row; r < 64; r += 16) {
            float4 v = *(const float4*)&g_Q[base + (size_t)(q0 + r) * D_ + c4];
            v.x *= SCALE; v.y *= SCALE; v.z *= SCALE; v.w *= SCALE;
            *(float4*)&Qs[r * LDT + c4] = v;
        }
    }
    if (tid < 64) { m_s[tid] = -1e30f; l_s[tid] = 0.0f; }
    for (int i = tid; i < 64 * 64; i += 256) Os[i] = 0.0f;

    const int t0 = wid * 2;   // each warp owns 2 of 16 (4x4) 16x16 tiles

    for (int kt = 0; kt < N_ / 64; kt++) {
        __syncthreads();   // protect Ks/Vs rewrite vs previous iter readers
        {
            const int row = tid >> 4;
            const int c4  = (tid & 15) * 4;
            const size_t kb = base + (size_t)(kt * 64) * D_;
            for (int r = row; r < 64; r += 16) {
                *(float4*)&Ks[r * LDT + c4] = *(const float4*)&g_K[kb + (size_t)r * D_ + c4];
                *(float4*)&Vs[r * LDT + c4] = *(const float4*)&g_V[kb + (size_t)r * D_ + c4];
            }
        }
        __syncthreads();

        // S = Qs * Ks^T  (64x64x64)
        #pragma unroll
        for (int t = t0; t < t0 + 2; t++) {
            const int tm = (t >> 2) * 16, tn = (t & 3) * 16;
            wmma::fragment<wmma::accumulator, 16, 16, 8, float> acc;
            wmma::fill_fragment(acc, 0.0f);
            #pragma unroll
            for (int kk = 0; kk < 64; kk += 8) {
                wmma::fragment<wmma::matrix_a, 16, 16, 8, wmma::precision::tf32,
                               wmma::row_major> a;
                wmma::fragment<wmma::matrix_b, 16, 16, 8, wmma::precision::tf32,
                               wmma::col_major> bf;
                wmma::load_matrix_sync(a, &Qs[tm * LDT + kk], LDT);
                wmma::load_matrix_sync(bf, &Ks[tn * LDT + kk], LDT);
                #pragma unroll
                for (int e = 0; e < a.num_elements; e++)
                    a.x[e] = wmma::__float_to_tf32(a.x[e]);
                #pragma unroll
                for (int e = 0; e < bf.num_elements; e++)
                    bf.x[e] = wmma::__float_to_tf32(bf.x[e]);
                wmma::mma_sync(acc, a, bf, acc);
            }
            wmma::store_matrix_sync(&Ss[tm * LDT + tn], acc, LDT, wmma::mem_row_major);
        }
        __syncthreads();

        // Online softmax row update (one thread per query row)
        if (tid < 64) {
            const int r = tid;
            const float m_old = m_s[r];
            float mx = m_old;
            #pragma unroll 8
            for (int j = 0; j < 64; j++) mx = fmaxf(mx, Ss[r * LDT + j]);
            const float sc = __expf(m_old - mx);
            float sum = 0.0f;
            #pragma unroll 8
            for (int j = 0; j < 64; j++) {
                const float p = __expf(Ss[r * LDT + j] - mx);
                Ss[r * LDT + j] = p;
                sum += p;
            }
            l_s[r] = l_s[r] * sc + sum;
            m_s[r] = mx;
            sc_s[r] = sc;
        }
        __syncthreads();

        // PV = P * V  (64x64x64) -> stage into Ks (free now)
        #pragma unroll
        for (int t = t0; t < t0 + 2; t++) {
            const int tm = (t >> 2) * 16, tn = (t & 3) * 16;
            wmma::fragment<wmma::accumulator, 16, 16, 8, float> acc;
            wmma::fill_fragment(acc, 0.0f);
            #pragma unroll
            for (int kk = 0; kk < 64; kk += 8) {
                wmma::fragment<wmma::matrix_a, 16, 16, 8, wmma::precision::tf32,
                               wmma::row_major> a;
                wmma::fragment<wmma::matrix_b, 16, 16, 8, wmma::precision::tf32,
                               wmma::row_major> bf;
                wmma::load_matrix_sync(a, &Ss[tm * LDT + kk], LDT);
                wmma::load_matrix_sync(bf, &Vs[kk * LDT + tn], LDT);
                #pragma unroll
                for (int e = 0; e < a.num_elements; e++)
                    a.x[e] = wmma::__float_to_tf32(a.x[e]);
                #pragma unroll
                for (int e = 0; e < bf.num_elements; e++)
                    bf.x[e] = wmma::__float_to_tf32(bf.x[e]);
                wmma::mma_sync(acc, a, bf, acc);
            }
            wmma::store_matrix_sync(&Ks[tm * LDT + tn], acc, LDT, wmma::mem_row_major);
        }
        __syncthreads();

        // O = O * exp(m_old - m_new) + PV
        for (int i = tid; i < 64 * 64; i += 256) {
            const int r = i >> 6, cc = i & 63;
            Os[i] = Os[i] * sc_s[r] + Ks[r * LDT + cc];
        }
    }
    __syncthreads();

    // Normalize and write out
    for (int i = tid; i < 64 * 64; i += 256) {
        const int r = i >> 6, cc = i & 63;
        g_AO[base + (size_t)(q0 + r) * D_ + cc] = Os[i] / l_s[r];
    }
}

// ---------------------------------------------------------------------------
// Launch
// ---------------------------------------------------------------------------
static constexpr size_t ATTN_SMEM =
    (4 * 64 * LDT + 64 * 64 + 3 * 64) * sizeof(float);   // 90880 bytes

extern "C" void kernel_launch(void* const* d_in, const int* in_sizes, int n_in,
                              void* d_out, int out_size)
{
    const float* q  = (const float*)d_in[0];
    const float* k  = (const float*)d_in[1];
    const float* v  = (const float*)d_in[2];
    const float* Wq = (const float*)d_in[3];
    const float* bq = (const float*)d_in[4];
    const float* Wk = (const float*)d_in[5];
    const float* bk = (const float*)d_in[6];
    const float* Wv = (const float*)d_in[7];
    const float* bv = (const float*)d_in[8];
    const float* Wo = (const float*)d_in[9];
    const float* bo = (const float*)d_in[10];
    float* out = (float*)d_out;

    float *pQ, *pK, *pV, *pAO;
    cudaGetSymbolAddress((void**)&pQ,  g_Q);
    cudaGetSymbolAddress((void**)&pK,  g_K);
    cudaGetSymbolAddress((void**)&pV,  g_V);
    cudaGetSymbolAddress((void**)&pAO, g_AO);

    cudaFuncSetAttribute(attn_kernel,
                         cudaFuncAttributeMaxDynamicSharedMemorySize,
                         (int)ATTN_SMEM);

    const dim3 ggrid(D_ / BN, M_TOT / BM);   // (8, 32)
    gemm_xwT_bias<<<ggrid, 256>>>(q, Wq, bq, pQ);
    gemm_xwT_bias<<<ggrid, 256>>>(k, Wk, bk, pK);
    gemm_xwT_bias<<<ggrid, 256>>>(v, Wv, bv, pV);

    attn_kernel<<<dim3(N_ / 64, H_, B_), 256, ATTN_SMEM>>>();

    gemm_xwT_bias<<<ggrid, 256>>>(pAO, Wo, bo, out);
}

// round 2
// speedup vs baseline: 1.6261x; 1.6261x over previous
#include <cuda_runtime.h>
#include <mma.h>
#include <cstdio>

using namespace nvcuda;

#define B_    2
#define N_    2048
#define D_    1024
#define H_    16
#define DK_   64
#define M_TOT (B_ * N_)
static constexpr float SCALE = 0.125f;   // DK^-0.5

__device__ float g_Q[M_TOT * D_];
__device__ float g_K[M_TOT * D_];
__device__ float g_V[M_TOT * D_];
__device__ float g_AO[M_TOT * D_];

// ---------------------------------------------------------------------------
// helpers
// ---------------------------------------------------------------------------
__device__ __forceinline__ unsigned f2tf32(float f) {
    unsigned u;
    asm("cvt.rna.tf32.f32 %0, %1;" : "=r"(u) : "f"(f));
    return u;
}

__device__ __forceinline__ void mma_tf32(
    float& c0, float& c1, float& c2, float& c3,
    unsigned a0, unsigned a1, unsigned a2, unsigned a3,
    unsigned b0, unsigned b1)
{
    asm volatile(
        "mma.sync.aligned.m16n8k8.row.col.f32.tf32.tf32.f32 "
        "{%0,%1,%2,%3}, {%4,%5,%6,%7}, {%8,%9}, {%0,%1,%2,%3};\n"
        : "+f"(c0), "+f"(c1), "+f"(c2), "+f"(c3)
        : "r"(a0), "r"(a1), "r"(a2), "r"(a3), "r"(b0), "r"(b1));
}

// ---------------------------------------------------------------------------
// GEMM: out[m,n] = sum_k X[m,k] * W[n,k] + bias[n]   (tf32 WMMA, reg-prefetch)
// ---------------------------------------------------------------------------
#define BM 128
#define BN 128
#define BK 32
#define LDA_S (BK + 4)

__global__ __launch_bounds__(256) void gemm_xwT_bias(
    const float* __restrict__ X, const float* __restrict__ W,
    const float* __restrict__ bias, float* __restrict__ out)
{
    __shared__ float As[BM][LDA_S];
    __shared__ float Bs[BN][LDA_S];
    __shared__ float bias_s[16][BN];

    const int tid = threadIdx.x;
    const int wid = tid >> 5;
    const int m0 = blockIdx.y * BM;
    const int n0 = blockIdx.x * BN;
    const int warp_m = wid >> 2;
    const int warp_n = wid & 3;

    for (int i = tid; i < 16 * BN; i += 256)
        bias_s[i >> 7][i & 127] = bias[n0 + (i & 127)];
    __syncthreads();

    wmma::fragment<wmma::accumulator, 16, 16, 8, float> c[4][2];
    #pragma unroll
    for (int i = 0; i < 4; i++)
        #pragma unroll
        for (int j = 0; j < 2; j++)
            wmma::load_matrix_sync(c[i][j], &bias_s[0][warp_n * 32 + j * 16],
                                   BN, wmma::mem_row_major);

    const int lrow = tid >> 3;
    const int lc4  = (tid & 7) * 4;

    float4 ra[4], rb[4];
    #pragma unroll
    for (int i = 0; i < 4; i++) {
        ra[i] = *(const float4*)&X[(size_t)(m0 + lrow + 32 * i) * D_ + lc4];
        rb[i] = *(const float4*)&W[(size_t)(n0 + lrow + 32 * i) * D_ + lc4];
    }

    for (int k0 = 0; k0 < D_; k0 += BK) {
        __syncthreads();
        #pragma unroll
        for (int i = 0; i < 4; i++) {
            *(float4*)&As[lrow + 32 * i][lc4] = ra[i];
            *(float4*)&Bs[lrow + 32 * i][lc4] = rb[i];
        }
        __syncthreads();
        if (k0 + BK < D_) {
            #pragma unroll
            for (int i = 0; i < 4; i++) {
                ra[i] = *(const float4*)&X[(size_t)(m0 + lrow + 32 * i) * D_ + k0 + BK + lc4];
                rb[i] = *(const float4*)&W[(size_t)(n0 + lrow + 32 * i) * D_ + k0 + BK + lc4];
            }
        }

        #pragma unroll
        for (int kk = 0; kk < BK; kk += 8) {
            wmma::fragment<wmma::matrix_a, 16, 16, 8, wmma::precision::tf32,
                           wmma::row_major> a[4];
            wmma::fragment<wmma::matrix_b, 16, 16, 8, wmma::precision::tf32,
                           wmma::col_major> b[2];
            #pragma unroll
            for (int i = 0; i < 4; i++) {
                wmma::load_matrix_sync(a[i], &As[warp_m * 64 + i * 16][kk], LDA_S);
                #pragma unroll
                for (int e = 0; e < a[i].num_elements; e++)
                    a[i].x[e] = wmma::__float_to_tf32(a[i].x[e]);
            }
            #pragma unroll
            for (int j = 0; j < 2; j++) {
                wmma::load_matrix_sync(b[j], &Bs[warp_n * 32 + j * 16][kk], LDA_S);
                #pragma unroll
                for (int e = 0; e < b[j].num_elements; e++)
                    b[j].x[e] = wmma::__float_to_tf32(b[j].x[e]);
            }
            #pragma unroll
            for (int i = 0; i < 4; i++)
                #pragma unroll
                for (int j = 0; j < 2; j++)
                    wmma::mma_sync(c[i][j], a[i], b[j], c[i][j]);
        }
    }

    #pragma unroll
    for (int i = 0; i < 4; i++)
        #pragma unroll
        for (int j = 0; j < 2; j++)
            wmma::store_matrix_sync(
                &out[(size_t)(m0 + warp_m * 64 + i * 16) * D_ +
                     n0 + warp_n * 32 + j * 16],
                c[i][j], D_, wmma::mem_row_major);
}

// ---------------------------------------------------------------------------
// Register-resident flash attention.
// Block: 256 threads (8 warps) x 128 queries (16 rows/warp). Key tiles of 64.
// Q fragments + O accumulator + S/P live in registers; softmax via shfl.
// ---------------------------------------------------------------------------
#define LDK 68
#define LDV 72
#define LDP 68
// smem floats: K 64*68, V 64*72, P 8*16*68
static constexpr int ATTN_SMEM_F = 64 * LDK + 64 * LDV + 8 * 16 * LDP;
static constexpr size_t ATTN_SMEM = ATTN_SMEM_F * sizeof(float);  // 70656 B

__global__ __launch_bounds__(256, 2) void attn_kernel()
{
    extern __shared__ float sm[];
    float* Ks = sm;                    // [64][LDK]  tf32-rounded
    float* Vs = Ks + 64 * LDK;         // [64][LDV]  tf32-rounded
    float* Pw = Vs + 64 * LDV;         // per-warp [16][LDP]

    const int tid  = threadIdx.x;
    const int wid  = tid >> 5;
    const int lane = tid & 31;
    const int rA   = lane >> 2;        // 0..7
    const int rB   = rA + 8;
    const int cj   = lane & 3;         // 0..3

    const int q0g = blockIdx.x * 128;
    const int h   = blockIdx.y;
    const int b   = blockIdx.z;
    const size_t base = (size_t)b * N_ * D_ + (size_t)h * DK_;

    float* Pm = Pw + wid * 16 * LDP;

    // ---- preload Q fragments (scaled, tf32) ----
    const float* qp = g_Q + base + (size_t)(q0g + wid * 16) * D_;
    unsigned qa[8][4];
    #pragma unroll
    for (int k0 = 0; k0 < 8; k0++) {
        qa[k0][0] = f2tf32(qp[(size_t)rA * D_ + k0 * 8 + cj]     * SCALE);
        qa[k0][1] = f2tf32(qp[(size_t)rB * D_ + k0 * 8 + cj]     * SCALE);
        qa[k0][2] = f2tf32(qp[(size_t)rA * D_ + k0 * 8 + cj + 4] * SCALE);
        qa[k0][3] = f2tf32(qp[(size_t)rB * D_ + k0 * 8 + cj + 4] * SCALE);
    }

    float o[8][4];
    #pragma unroll
    for (int n = 0; n < 8; n++)
        #pragma unroll
        for (int e = 0; e < 4; e++) o[n][e] = 0.0f;
    float mA = -1e30f, mB = -1e30f, lA = 0.0f, lB = 0.0f;

    for (int kt = 0; kt < N_ / 64; kt++) {
        __syncthreads();   // all warps done reading previous K/V tiles
        {
            const int r  = tid >> 2;          // 0..63
            const int c4 = (tid & 3) * 16;    // 0,16,32,48
            const size_t kb = base + (size_t)(kt * 64) * D_;
            #pragma unroll
            for (int cc = 0; cc < 16; cc += 4) {
                float4 kv = *(const float4*)&g_K[kb + (size_t)r * D_ + c4 + cc];
                Ks[r * LDK + c4 + cc + 0] = __uint_as_float(f2tf32(kv.x));
                Ks[r * LDK + c4 + cc + 1] = __uint_as_float(f2tf32(kv.y));
                Ks[r * LDK + c4 + cc + 2] = __uint_as_float(f2tf32(kv.z));
                Ks[r * LDK + c4 + cc + 3] = __uint_as_float(f2tf32(kv.w));
                float4 vv = *(const float4*)&g_V[kb + (size_t)r * D_ + c4 + cc];
                Vs[r * LDV + c4 + cc + 0] = __uint_as_float(f2tf32(vv.x));
                Vs[r * LDV + c4 + cc + 1] = __uint_as_float(f2tf32(vv.y));
                Vs[r * LDV + c4 + cc + 2] = __uint_as_float(f2tf32(vv.z));
                Vs[r * LDV + c4 + cc + 3] = __uint_as_float(f2tf32(vv.w));
            }
        }
        __syncthreads();

        // ---- S = Q K^T  (16 x 64 per warp) ----
        float s[8][4];
        #pragma unroll
        for (int t = 0; t < 8; t++) {
            float c0 = 0, c1 = 0, c2 = 0, c3 = 0;
            #pragma unroll
            for (int k0 = 0; k0 < 8; k0++) {
                unsigned b0 = __float_as_uint(Ks[(t * 8 + rA) * LDK + k0 * 8 + cj]);
                unsigned b1 = __float_as_uint(Ks[(t * 8 + rA) * LDK + k0 * 8 + cj + 4]);
                mma_tf32(c0, c1, c2, c3,
                         qa[k0][0], qa[k0][1], qa[k0][2], qa[k0][3], b0, b1);
            }
            s[t][0] = c0; s[t][1] = c1; s[t][2] = c2; s[t][3] = c3;
        }

        // ---- online softmax (registers + shfl) ----
        float mxA = -1e30f, mxB = -1e30f;
        #pragma unroll
        for (int t = 0; t < 8; t++) {
            mxA = fmaxf(mxA, fmaxf(s[t][0], s[t][1]));
            mxB = fmaxf(mxB, fmaxf(s[t][2], s[t][3]));
        }
        mxA = fmaxf(mxA, __shfl_xor_sync(0xffffffffu, mxA, 1));
        mxA = fmaxf(mxA, __shfl_xor_sync(0xffffffffu, mxA, 2));
        mxB = fmaxf(mxB, __shfl_xor_sync(0xffffffffu, mxB, 1));
        mxB = fmaxf(mxB, __shfl_xor_sync(0xffffffffu, mxB, 2));

        const float mA_new = fmaxf(mA, mxA);
        const float mB_new = fmaxf(mB, mxB);
        const float scA = __expf(mA - mA_new);
        const float scB = __expf(mB - mB_new);
        mA = mA_new; mB = mB_new;

        float sumA = 0.0f, sumB = 0.0f;
        #pragma unroll
        for (int t = 0; t < 8; t++) {
            s[t][0] = __expf(s[t][0] - mA_new);
            s[t][1] = __expf(s[t][1] - mA_new);
            s[t][2] = __expf(s[t][2] - mB_new);
            s[t][3] = __expf(s[t][3] - mB_new);
            sumA += s[t][0] + s[t][1];
            sumB += s[t][2] + s[t][3];
        }
        sumA += __shfl_xor_sync(0xffffffffu, sumA, 1);
        sumA += __shfl_xor_sync(0xffffffffu, sumA, 2);
        sumB += __shfl_xor_sync(0xffffffffu, sumB, 1);
        sumB += __shfl_xor_sync(0xffffffffu, sumB, 2);
        lA = lA * scA + sumA;
        lB = lB * scB + sumB;

        #pragma unroll
        for (int n = 0; n < 8; n++) {
            o[n][0] *= scA; o[n][1] *= scA;
            o[n][2] *= scB; o[n][3] *= scB;
        }

        // ---- stage P (tf32) to per-warp smem pad ----
        #pragma unroll
        for (int t = 0; t < 8; t++) {
            float2 pa = make_float2(__uint_as_float(f2tf32(s[t][0])),
                                    __uint_as_float(f2tf32(s[t][1])));
            float2 pb = make_float2(__uint_as_float(f2tf32(s[t][2])),
                                    __uint_as_float(f2tf32(s[t][3])));
            *(float2*)&Pm[rA * LDP + t * 8 + 2 * cj] = pa;
            *(float2*)&Pm[rB * LDP + t * 8 + 2 * cj] = pb;
        }
        __syncwarp();

        // ---- O += P V  (16 x 64 per warp) ----
        #pragma unroll
        for (int k0 = 0; k0 < 8; k0++) {
            unsigned a0 = __float_as_uint(Pm[rA * LDP + k0 * 8 + cj]);
            unsigned a1 = __float_as_uint(Pm[rB * LDP + k0 * 8 + cj]);
            unsigned a2 = __float_as_uint(Pm[rA * LDP + k0 * 8 + cj + 4]);
            unsigned a3 = __float_as_uint(Pm[rB * LDP + k0 * 8 + cj + 4]);
            #pragma unroll
            for (int n = 0; n < 8; n++) {
                unsigned b0 = __float_as_uint(Vs[(k0 * 8 + cj) * LDV + n * 8 + rA]);
                unsigned b1 = __float_as_uint(Vs[(k0 * 8 + cj + 4) * LDV + n * 8 + rA]);
                mma_tf32(o[n][0], o[n][1], o[n][2], o[n][3],
                         a0, a1, a2, a3, b0, b1);
            }
        }
        __syncwarp();
    }

    // ---- normalize + write ----
    const float invA = 1.0f / lA;
    const float invB = 1.0f / lB;
    float* op = g_AO + base + (size_t)(q0g + wid * 16) * D_;
    #pragma unroll
    for (int n = 0; n < 8; n++) {
        *(float2*)&op[(size_t)rA * D_ + n * 8 + 2 * cj] =
            make_float2(o[n][0] * invA, o[n][1] * invA);
        *(float2*)&op[(size_t)rB * D_ + n * 8 + 2 * cj] =
            make_float2(o[n][2] * invB, o[n][3] * invB);
    }
}

// ---------------------------------------------------------------------------
extern "C" void kernel_launch(void* const* d_in, const int* in_sizes, int n_in,
                              void* d_out, int out_size)
{
    const float* q  = (const float*)d_in[0];
    const float* k  = (const float*)d_in[1];
    const float* v  = (const float*)d_in[2];
    const float* Wq = (const float*)d_in[3];
    const float* bq = (const float*)d_in[4];
    const float* Wk = (const float*)d_in[5];
    const float* bk = (const float*)d_in[6];
    const float* Wv = (const float*)d_in[7];
    const float* bv = (const float*)d_in[8];
    const float* Wo = (const float*)d_in[9];
    const float* bo = (const float*)d_in[10];
    float* out = (float*)d_out;

    float *pQ, *pK, *pV, *pAO;
    cudaGetSymbolAddress((void**)&pQ,  g_Q);
    cudaGetSymbolAddress((void**)&pK,  g_K);
    cudaGetSymbolAddress((void**)&pV,  g_V);
    cudaGetSymbolAddress((void**)&pAO, g_AO);

    cudaFuncSetAttribute(attn_kernel,
                         cudaFuncAttributeMaxDynamicSharedMemorySize,
                         (int)ATTN_SMEM);

    const dim3 ggrid(D_ / BN, M_TOT / BM);   // (8, 32)
    gemm_xwT_bias<<<ggrid, 256>>>(q, Wq, bq, pQ);
    gemm_xwT_bias<<<ggrid, 256>>>(k, Wk, bk, pK);
    gemm_xwT_bias<<<ggrid, 256>>>(v, Wv, bv, pV);

    attn_kernel<<<dim3(N_ / 128, H_, B_), 256, ATTN_SMEM>>>();

    gemm_xwT_bias<<<ggrid, 256>>>(pAO, Wo, bo, out);
}

// round 3
// speedup vs baseline: 5.2718x; 3.2419x over previous
#include <cuda_runtime.h>
#include <cuda_fp16.h>

#define B_    2
#define N_    2048
#define D_    1024
#define H_    16
#define DK_   64
#define M_TOT (B_ * N_)
static constexpr float SCALE = 0.125f;   // DK^-0.5

// fp16 scratch
__device__ half g_Q [(size_t)M_TOT * D_];
__device__ half g_K [(size_t)M_TOT * D_];
__device__ half g_VT[(size_t)D_ * M_TOT];   // [dim][token] (pre-transposed)
__device__ half g_AO[(size_t)M_TOT * D_];

// ---------------------------------------------------------------------------
__device__ __forceinline__ unsigned pack_h2(float a, float b) {
    half2 h = __floats2half2_rn(a, b);
    return *reinterpret_cast<unsigned*>(&h);
}

__device__ __forceinline__ void mma_f16(
    float* c, const unsigned* a, unsigned b0, unsigned b1)
{
    asm volatile(
        "mma.sync.aligned.m16n8k16.row.col.f32.f16.f16.f32 "
        "{%0,%1,%2,%3}, {%4,%5,%6,%7}, {%8,%9}, {%0,%1,%2,%3};\n"
        : "+f"(c[0]), "+f"(c[1]), "+f"(c[2]), "+f"(c[3])
        : "r"(a[0]), "r"(a[1]), "r"(a[2]), "r"(a[3]), "r"(b0), "r"(b1));
}

// ---------------------------------------------------------------------------
// GEMM: out[m,n] = sum_k A[m,k] * Bw[n,k] + bias    (K = 1024 fixed)
// fp16 HMMA m16n8k16, half conversion at smem store, 2-stage pipeline.
// Block 128x128x32, 256 threads, warp tile 64x32.
// ---------------------------------------------------------------------------
#define BKP 40   // half stride (32 + 8 pad)

template<typename TA, typename TOUT, bool BIAS_ROW>
__global__ __launch_bounds__(256, 2) void gemm_h(
    const TA* __restrict__ A, const float* __restrict__ Bw,
    const float* __restrict__ bias, TOUT* __restrict__ out, int NC)
{
    __shared__ half As[2][128 * BKP];
    __shared__ half Bs[2][128 * BKP];

    const int tid  = threadIdx.x;
    const int wid  = tid >> 5, lane = tid & 31;
    const int rA   = lane >> 2, cj = lane & 3;
    const int m0   = blockIdx.y * 128, n0 = blockIdx.x * 128;
    const int wm   = wid >> 2, wn = wid & 3;

    float c[4][4][4];
    #pragma unroll
    for (int i = 0; i < 4; i++)
        #pragma unroll
        for (int j = 0; j < 4; j++)
            #pragma unroll
            for (int e = 0; e < 4; e++) c[i][j][e] = 0.0f;

    const int lr  = tid >> 3, lc4 = (tid & 7) * 4;   // fp32 loader
    const int hr  = tid >> 2, hc8 = (tid & 3) * 8;   // half loader

    float4 raf[4]; uint4 rah[2]; float4 rbf[4];

    auto loadA = [&](int k0) {
        if constexpr (sizeof(TA) == 4) {
            #pragma unroll
            for (int i = 0; i < 4; i++)
                raf[i] = *(const float4*)&A[(size_t)(m0 + lr + 32 * i) * D_ + k0 + lc4];
        } else {
            #pragma unroll
            for (int i = 0; i < 2; i++)
                rah[i] = *(const uint4*)&A[(size_t)(m0 + hr + 64 * i) * D_ + k0 + hc8];
        }
    };
    auto loadB = [&](int k0) {
        #pragma unroll
        for (int i = 0; i < 4; i++)
            rbf[i] = *(const float4*)&Bw[(size_t)(n0 + lr + 32 * i) * D_ + k0 + lc4];
    };
    auto storeA = [&](int s) {
        if constexpr (sizeof(TA) == 4) {
            #pragma unroll
            for (int i = 0; i < 4; i++) {
                uint2 u;
                u.x = pack_h2(raf[i].x, raf[i].y);
                u.y = pack_h2(raf[i].z, raf[i].w);
                *(uint2*)&As[s][(lr + 32 * i) * BKP + lc4] = u;
            }
        } else {
            #pragma unroll
            for (int i = 0; i < 2; i++)
                *(uint4*)&As[s][(hr + 64 * i) * BKP + hc8] = rah[i];
        }
    };
    auto storeB = [&](int s) {
        #pragma unroll
        for (int i = 0; i < 4; i++) {
            uint2 u;
            u.x = pack_h2(rbf[i].x, rbf[i].y);
            u.y = pack_h2(rbf[i].z, rbf[i].w);
            *(uint2*)&Bs[s][(lr + 32 * i) * BKP + lc4] = u;
        }
    };

    loadA(0); loadB(0);

    #pragma unroll 1
    for (int kt = 0; kt < 32; kt++) {
        const int s = kt & 1;
        storeA(s); storeB(s);
        __syncthreads();
        if (kt < 31) { loadA((kt + 1) * 32); loadB((kt + 1) * 32); }

        #pragma unroll
        for (int kk = 0; kk < 2; kk++) {
            unsigned a[4][4], bb[4][2];
            #pragma unroll
            for (int mt = 0; mt < 4; mt++) {
                const half* p = &As[s][(wm * 64 + mt * 16 + rA) * BKP + kk * 16 + 2 * cj];
                a[mt][0] = *(const unsigned*)p;
                a[mt][1] = *(const unsigned*)(p + 8 * BKP);
                a[mt][2] = *(const unsigned*)(p + 8);
                a[mt][3] = *(const unsigned*)(p + 8 * BKP + 8);
            }
            #pragma unroll
            for (int nt = 0; nt < 4; nt++) {
                const half* p = &Bs[s][(wn * 32 + nt * 8 + rA) * BKP + kk * 16 + 2 * cj];
                bb[nt][0] = *(const unsigned*)p;
                bb[nt][1] = *(const unsigned*)(p + 8);
            }
            #pragma unroll
            for (int mt = 0; mt < 4; mt++)
                #pragma unroll
                for (int nt = 0; nt < 4; nt++)
                    mma_f16(c[mt][nt], a[mt], bb[nt][0], bb[nt][1]);
        }
    }

    // epilogue
    #pragma unroll
    for (int mt = 0; mt < 4; mt++) {
        const int r0 = m0 + wm * 64 + mt * 16 + rA;
        #pragma unroll
        for (int nt = 0; nt < 4; nt++) {
            const int nc = n0 + wn * 32 + nt * 8 + 2 * cj;
            float v0 = c[mt][nt][0], v1 = c[mt][nt][1];
            float v2 = c[mt][nt][2], v3 = c[mt][nt][3];
            if (BIAS_ROW) {
                const float br0 = bias[r0], br1 = bias[r0 + 8];
                v0 += br0; v1 += br0; v2 += br1; v3 += br1;
            } else {
                const float b0v = bias[nc], b1v = bias[nc + 1];
                v0 += b0v; v1 += b1v; v2 += b0v; v3 += b1v;
            }
            if constexpr (sizeof(TOUT) == 4) {
                *(float2*)&out[(size_t)r0 * NC + nc]       = make_float2(v0, v1);
                *(float2*)&out[(size_t)(r0 + 8) * NC + nc] = make_float2(v2, v3);
            } else {
                *(unsigned*)&out[(size_t)r0 * NC + nc]       = pack_h2(v0, v1);
                *(unsigned*)&out[(size_t)(r0 + 8) * NC + nc] = pack_h2(v2, v3);
            }
        }
    }
}

// ---------------------------------------------------------------------------
// Flash attention, fp16 m16n8k16. 8 warps x 16 query rows = 128 q/block.
// P stays in registers (S C-frag == PV A-frag layout). V pre-transposed.
// ---------------------------------------------------------------------------
#define LDK  72
#define LDVT 72

__global__ __launch_bounds__(256, 2) void attn_kernel()
{
    __shared__ half Ks[64 * LDK];    // [key][feat]
    __shared__ half Vt[64 * LDVT];   // [dcol][key]

    const int tid  = threadIdx.x, wid = tid >> 5, lane = tid & 31;
    const int rA   = lane >> 2, rB = rA + 8, cj = lane & 3;
    const int q0g  = blockIdx.x * 128;
    const int h    = blockIdx.y;
    const int b    = blockIdx.z;

    // Q fragments (register-resident for whole kernel)
    const half* qp = g_Q + (size_t)(b * N_ + q0g + wid * 16) * D_ + h * DK_;
    unsigned qa[4][4];
    #pragma unroll
    for (int kk = 0; kk < 4; kk++) {
        qa[kk][0] = *(const unsigned*)&qp[(size_t)rA * D_ + kk * 16 + 2 * cj];
        qa[kk][1] = *(const unsigned*)&qp[(size_t)rB * D_ + kk * 16 + 2 * cj];
        qa[kk][2] = *(const unsigned*)&qp[(size_t)rA * D_ + kk * 16 + 2 * cj + 8];
        qa[kk][3] = *(const unsigned*)&qp[(size_t)rB * D_ + kk * 16 + 2 * cj + 8];
    }

    float o[8][4];
    #pragma unroll
    for (int n = 0; n < 8; n++)
        #pragma unroll
        for (int e = 0; e < 4; e++) o[n][e] = 0.0f;
    float mA = -1e30f, mB = -1e30f, lA = 0.0f, lB = 0.0f;

    const int fr = tid >> 3, fc8 = (tid & 7) * 8;

    for (int kt = 0; kt < 32; kt++) {
        __syncthreads();
        #pragma unroll
        for (int i = 0; i < 2; i++) {
            *(uint4*)&Ks[(fr + 32 * i) * LDK + fc8] =
                *(const uint4*)&g_K[(size_t)(b * N_ + kt * 64 + fr + 32 * i) * D_ + h * DK_ + fc8];
            *(uint4*)&Vt[(fr + 32 * i) * LDVT + fc8] =
                *(const uint4*)&g_VT[(size_t)(h * DK_ + fr + 32 * i) * M_TOT + b * N_ + kt * 64 + fc8];
        }
        __syncthreads();

        // ---- S = Q K^T ----
        float s[8][4];
        #pragma unroll
        for (int t = 0; t < 8; t++) {
            s[t][0] = s[t][1] = s[t][2] = s[t][3] = 0.0f;
            #pragma unroll
            for (int kk = 0; kk < 4; kk++) {
                const half* p = &Ks[(t * 8 + rA) * LDK + kk * 16 + 2 * cj];
                mma_f16(s[t], qa[kk], *(const unsigned*)p, *(const unsigned*)(p + 8));
            }
            s[t][0] *= SCALE; s[t][1] *= SCALE;
            s[t][2] *= SCALE; s[t][3] *= SCALE;
        }

        // ---- online softmax ----
        float mxA = -1e30f, mxB = -1e30f;
        #pragma unroll
        for (int t = 0; t < 8; t++) {
            mxA = fmaxf(mxA, fmaxf(s[t][0], s[t][1]));
            mxB = fmaxf(mxB, fmaxf(s[t][2], s[t][3]));
        }
        mxA = fmaxf(mxA, __shfl_xor_sync(0xffffffffu, mxA, 1));
        mxA = fmaxf(mxA, __shfl_xor_sync(0xffffffffu, mxA, 2));
        mxB = fmaxf(mxB, __shfl_xor_sync(0xffffffffu, mxB, 1));
        mxB = fmaxf(mxB, __shfl_xor_sync(0xffffffffu, mxB, 2));

        const float mA_new = fmaxf(mA, mxA);
        const float mB_new = fmaxf(mB, mxB);
        const float scA = __expf(mA - mA_new);
        const float scB = __expf(mB - mB_new);
        mA = mA_new; mB = mB_new;

        float sumA = 0.0f, sumB = 0.0f;
        #pragma unroll
        for (int t = 0; t < 8; t++) {
            s[t][0] = __expf(s[t][0] - mA_new);
            s[t][1] = __expf(s[t][1] - mA_new);
            s[t][2] = __expf(s[t][2] - mB_new);
            s[t][3] = __expf(s[t][3] - mB_new);
            sumA += s[t][0] + s[t][1];
            sumB += s[t][2] + s[t][3];
        }
        sumA += __shfl_xor_sync(0xffffffffu, sumA, 1);
        sumA += __shfl_xor_sync(0xffffffffu, sumA, 2);
        sumB += __shfl_xor_sync(0xffffffffu, sumB, 1);
        sumB += __shfl_xor_sync(0xffffffffu, sumB, 2);
        lA = lA * scA + sumA;
        lB = lB * scB + sumB;

        #pragma unroll
        for (int n = 0; n < 8; n++) {
            o[n][0] *= scA; o[n][1] *= scA;
            o[n][2] *= scB; o[n][3] *= scB;
        }

        // ---- pack P into A-fragments (registers only) ----
        unsigned p[4][4];
        #pragma unroll
        for (int kk = 0; kk < 4; kk++) {
            p[kk][0] = pack_h2(s[2 * kk][0],     s[2 * kk][1]);
            p[kk][1] = pack_h2(s[2 * kk][2],     s[2 * kk][3]);
            p[kk][2] = pack_h2(s[2 * kk + 1][0], s[2 * kk + 1][1]);
            p[kk][3] = pack_h2(s[2 * kk + 1][2], s[2 * kk + 1][3]);
        }

        // ---- O += P V ----
        #pragma unroll
        for (int kk = 0; kk < 4; kk++)
            #pragma unroll
            for (int nt = 0; nt < 8; nt++) {
                const half* vp = &Vt[(nt * 8 + rA) * LDVT + kk * 16 + 2 * cj];
                mma_f16(o[nt], p[kk], *(const unsigned*)vp, *(const unsigned*)(vp + 8));
            }
    }

    // ---- normalize + write (half) ----
    const float invA = 1.0f / lA, invB = 1.0f / lB;
    half* op = g_AO + (size_t)(b * N_ + q0g + wid * 16) * D_ + h * DK_;
    #pragma unroll
    for (int nt = 0; nt < 8; nt++) {
        *(unsigned*)&op[(size_t)rA * D_ + nt * 8 + 2 * cj] =
            pack_h2(o[nt][0] * invA, o[nt][1] * invA);
        *(unsigned*)&op[(size_t)rB * D_ + nt * 8 + 2 * cj] =
            pack_h2(o[nt][2] * invB, o[nt][3] * invB);
    }
}

// ---------------------------------------------------------------------------
extern "C" void kernel_launch(void* const* d_in, const int* in_sizes, int n_in,
                              void* d_out, int out_size)
{
    const float* q  = (const float*)d_in[0];
    const float* k  = (const float*)d_in[1];
    const float* v  = (const float*)d_in[2];
    const float* Wq = (const float*)d_in[3];
    const float* bq = (const float*)d_in[4];
    const float* Wk = (const float*)d_in[5];
    const float* bk = (const float*)d_in[6];
    const float* Wv = (const float*)d_in[7];
    const float* bv = (const float*)d_in[8];
    const float* Wo = (const float*)d_in[9];
    const float* bo = (const float*)d_in[10];
    float* out = (float*)d_out;

    half *pQ, *pK, *pVT, *pAO;
    cudaGetSymbolAddress((void**)&pQ,  g_Q);
    cudaGetSymbolAddress((void**)&pK,  g_K);
    cudaGetSymbolAddress((void**)&pVT, g_VT);
    cudaGetSymbolAddress((void**)&pAO, g_AO);

    const dim3 gproj(D_ / 128, M_TOT / 128);   // (8, 32)
    const dim3 gvt(M_TOT / 128, D_ / 128);     // (32, 8)

    // Q, K projections: out[token][dim] half
    gemm_h<float, half, false><<<gproj, 256>>>(q, Wq, bq, pQ, D_);
    gemm_h<float, half, false><<<gproj, 256>>>(k, Wk, bk, pK, D_);
    // V projection transposed: out[dim][token] half  (A = Wv rows=dim, B = v rows=token)
    gemm_h<float, half, true ><<<gvt,   256>>>(Wv, v, bv, pVT, M_TOT);

    attn_kernel<<<dim3(N_ / 128, H_, B_), 256>>>();

    // Output projection: A = AO (half), out fp32
    gemm_h<half, float, false><<<gproj, 256>>>(pAO, Wo, bo, out, D_);
}